// round 1
// baseline (speedup 1.0000x reference)
#include <cuda_runtime.h>
#include <cuda_bf16.h>

#define TM 128
#define TN 128
#define TK 16
#define INV_TAU 10.0f
#define MAX_B 8192

// Scratch (no allocations allowed): per-row streaming statistics.
__device__ float g_S[MAX_B];   // sum_{j != i} exp(sim_ij)
__device__ float g_P[MAX_B];   // sum over positives of sim_ij
__device__ int   g_C[MAX_B];   // count of positives

__global__ void zero_stats_kernel(int B) {
    int i = blockIdx.x * blockDim.x + threadIdx.x;
    if (i < B) { g_S[i] = 0.0f; g_P[i] = 0.0f; g_C[i] = 0; }
}

__global__ __launch_bounds__(256, 2)
void sim_stats_kernel(const float* __restrict__ E,
                      const long long* __restrict__ labels,
                      int B, int D) {
    __shared__ float As[TK][TM + 4];
    __shared__ float Bs[TK][TN + 4];
    __shared__ int   lA[TM];
    __shared__ int   lB[TN];
    __shared__ float sS[TM];
    __shared__ float sP[TM];
    __shared__ int   sC[TM];

    const int m0 = blockIdx.y * TM;
    const int n0 = blockIdx.x * TN;
    const int tid = threadIdx.x;
    const int tx = tid & 15;   // 0..15, column group
    const int ty = tid >> 4;   // 0..15, row group

    if (tid < TM) {
        lA[tid] = (int)labels[m0 + tid];
        lB[tid] = (int)labels[n0 + tid];
        sS[tid] = 0.0f; sP[tid] = 0.0f; sC[tid] = 0;
    }

    float acc[8][8];
    #pragma unroll
    for (int r = 0; r < 8; ++r)
        #pragma unroll
        for (int c = 0; c < 8; ++c) acc[r][c] = 0.0f;

    const int numTiles = D / TK;
    for (int t = 0; t < numTiles; ++t) {
        const int k0 = t * TK;
        // Load 128x16 A and B tiles, stored transposed As[k][m], via float4.
        #pragma unroll
        for (int l = 0; l < 2; ++l) {
            int idx = tid + l * 256;       // 0..511 float4 slots
            int m  = idx >> 2;             // 0..127
            int kq = idx & 3;              // 0..3
            float4 va = *reinterpret_cast<const float4*>(
                &E[(size_t)(m0 + m) * D + k0 + kq * 4]);
            As[kq * 4 + 0][m] = va.x;
            As[kq * 4 + 1][m] = va.y;
            As[kq * 4 + 2][m] = va.z;
            As[kq * 4 + 3][m] = va.w;
            float4 vb = *reinterpret_cast<const float4*>(
                &E[(size_t)(n0 + m) * D + k0 + kq * 4]);
            Bs[kq * 4 + 0][m] = vb.x;
            Bs[kq * 4 + 1][m] = vb.y;
            Bs[kq * 4 + 2][m] = vb.z;
            Bs[kq * 4 + 3][m] = vb.w;
        }
        __syncthreads();

        #pragma unroll
        for (int k = 0; k < TK; ++k) {
            float4 a0 = *reinterpret_cast<const float4*>(&As[k][ty * 8]);
            float4 a1 = *reinterpret_cast<const float4*>(&As[k][ty * 8 + 4]);
            float4 b0 = *reinterpret_cast<const float4*>(&Bs[k][tx * 8]);
            float4 b1 = *reinterpret_cast<const float4*>(&Bs[k][tx * 8 + 4]);
            float a[8] = {a0.x, a0.y, a0.z, a0.w, a1.x, a1.y, a1.z, a1.w};
            float b[8] = {b0.x, b0.y, b0.z, b0.w, b1.x, b1.y, b1.z, b1.w};
            #pragma unroll
            for (int r = 0; r < 8; ++r)
                #pragma unroll
                for (int c = 0; c < 8; ++c)
                    acc[r][c] = fmaf(a[r], b[c], acc[r][c]);
        }
        __syncthreads();
    }

    // Epilogue: scale by 1/tau, exp, mask diagonal & label matches.
    #pragma unroll
    for (int r = 0; r < 8; ++r) {
        const int mi = ty * 8 + r;
        const int i  = m0 + mi;
        const int li = lA[mi];
        float s = 0.0f, p = 0.0f;
        int   c = 0;
        #pragma unroll
        for (int cc = 0; cc < 8; ++cc) {
            const int nj = tx * 8 + cc;
            const int j  = n0 + nj;
            const float sim = acc[r][cc] * INV_TAU;
            const float e = __expf(sim);
            const bool offdiag = (j != i);
            if (offdiag) {
                s += e;
                if (lB[nj] == li) { p += sim; c++; }
            }
        }
        atomicAdd(&sS[mi], s);
        atomicAdd(&sP[mi], p);
        atomicAdd(&sC[mi], c);
    }
    __syncthreads();

    if (tid < TM) {
        atomicAdd(&g_S[m0 + tid], sS[tid]);
        atomicAdd(&g_P[m0 + tid], sP[tid]);
        atomicAdd(&g_C[m0 + tid], sC[tid]);
    }
}

__global__ void final_reduce_kernel(float* __restrict__ out, int B) {
    __shared__ float sLoss[256];
    __shared__ int   sCnt[256];
    const int tid = threadIdx.x;
    float loss = 0.0f;
    int   cnt = 0;
    for (int i = tid; i < B; i += 256) {
        const int c = g_C[i];
        if (c > 0) {
            const float lse = logf(g_S[i]);
            loss += lse - g_P[i] / (float)c;
            cnt++;
        }
    }
    sLoss[tid] = loss;
    sCnt[tid]  = cnt;
    __syncthreads();
    for (int s = 128; s > 0; s >>= 1) {
        if (tid < s) { sLoss[tid] += sLoss[tid + s]; sCnt[tid] += sCnt[tid + s]; }
        __syncthreads();
    }
    if (tid == 0) {
        int na = sCnt[0] > 0 ? sCnt[0] : 1;
        out[0] = sLoss[0] / (float)na;
    }
}

extern "C" void kernel_launch(void* const* d_in, const int* in_sizes, int n_in,
                              void* d_out, int out_size) {
    const float*     E      = (const float*)d_in[0];
    const long long* labels = (const long long*)d_in[1];
    float*           out    = (float*)d_out;

    const int B = in_sizes[1];
    const int D = in_sizes[0] / B;

    zero_stats_kernel<<<(B + 255) / 256, 256>>>(B);

    dim3 grid(B / TN, B / TM);
    sim_stats_kernel<<<grid, 256>>>(E, labels, B, D);

    final_reduce_kernel<<<1, 256>>>(out, B);
}

// round 3
// speedup vs baseline: 8.9011x; 8.9011x over previous
#include <cuda_runtime.h>
#include <cuda_bf16.h>
#include <cstdint>

#define B_SIZE 8192
#define D_SIZE 1024
#define TM 128
#define TN 128
#define KC 64                      // bf16 elems per K-chunk (128 bytes/row)
#define NCHUNK (D_SIZE / KC)       // 16
#define INV_TAU 10.0f

// ---------------- device scratch (no allocations allowed) ----------------
__device__ float g_S[B_SIZE];
__device__ float g_P[B_SIZE];
__device__ int   g_C[B_SIZE];
__device__ __align__(16) __nv_bfloat16 g_Ebf[B_SIZE * D_SIZE];

// ---------------- smem layout ----------------
#define STAGE_BYTES 32768          // A tile 16KB + B tile 16KB
#define OFF_B 16384
#define SM_MISC 65536
#define SM_LA  (SM_MISC + 0)       // int[128]
#define SM_LB  (SM_MISC + 512)
#define SM_RS  (SM_MISC + 1024)    // float[128]
#define SM_RP  (SM_MISC + 1536)
#define SM_RC  (SM_MISC + 2048)
#define SM_CS  (SM_MISC + 2560)
#define SM_CP  (SM_MISC + 3072)
#define SM_CC  (SM_MISC + 3584)
#define SMEM_TOTAL (SM_MISC + 4096)

// ---------------- helpers ----------------
__device__ __forceinline__ uint32_t smem_u32(const void* p) {
    uint32_t a;
    asm("{ .reg .u64 t; cvta.to.shared.u64 t, %1; cvt.u32.u64 %0, t; }" : "=r"(a) : "l"(p));
    return a;
}
__device__ __forceinline__ void cp_async16(uint32_t dst, const void* src) {
    asm volatile("cp.async.cg.shared.global [%0], [%1], 16;" :: "r"(dst), "l"(src));
}
__device__ __forceinline__ void cp_commit() { asm volatile("cp.async.commit_group;"); }

__device__ __forceinline__ void ldsm4(uint32_t addr, uint32_t& r0, uint32_t& r1,
                                      uint32_t& r2, uint32_t& r3) {
    asm volatile("ldmatrix.sync.aligned.m8n8.x4.shared.b16 {%0,%1,%2,%3}, [%4];"
                 : "=r"(r0), "=r"(r1), "=r"(r2), "=r"(r3) : "r"(addr));
}
__device__ __forceinline__ void mma16816(float* d, const uint32_t* a,
                                         uint32_t b0, uint32_t b1) {
    asm volatile(
        "mma.sync.aligned.m16n8k16.row.col.f32.bf16.bf16.f32 "
        "{%0,%1,%2,%3}, {%4,%5,%6,%7}, {%8,%9}, {%0,%1,%2,%3};"
        : "+f"(d[0]), "+f"(d[1]), "+f"(d[2]), "+f"(d[3])
        : "r"(a[0]), "r"(a[1]), "r"(a[2]), "r"(a[3]), "r"(b0), "r"(b1));
}

// fast e^x via 2^(x*log2e), degree-5 poly; valid for |x| <= ~14
__device__ __forceinline__ float fast_exp(float x) {
    const float LOG2E = 1.4426950408889634f;
    const float MAGIC = 12582912.0f;  // 1.5 * 2^23
    float y = x * LOG2E;
    float t = y + MAGIC;
    int   i = __float_as_int(t) - 0x4B400000;
    float f = y - (t - MAGIC);
    float p = 1.3333558e-3f;
    p = fmaf(p, f, 9.6181291e-3f);
    p = fmaf(p, f, 5.5504109e-2f);
    p = fmaf(p, f, 2.4022650e-1f);
    p = fmaf(p, f, 6.9314718e-1f);
    p = fmaf(p, f, 1.0f);
    return __int_as_float(__float_as_int(p) + (i << 23));
}

// ---------------- kernels ----------------
__global__ void zero_stats_kernel(int B) {
    int i = blockIdx.x * blockDim.x + threadIdx.x;
    if (i < B) { g_S[i] = 0.0f; g_P[i] = 0.0f; g_C[i] = 0; }
}

__global__ void convert_kernel(const float* __restrict__ E) {
    int idx = blockIdx.x * 256 + threadIdx.x;  // one float4 per thread
    float4 v = reinterpret_cast<const float4*>(E)[idx];
    __nv_bfloat162* hp = reinterpret_cast<__nv_bfloat162*>(g_Ebf);
    hp[idx * 2 + 0] = __nv_bfloat162(__float2bfloat16(v.x), __float2bfloat16(v.y));
    hp[idx * 2 + 1] = __nv_bfloat162(__float2bfloat16(v.z), __float2bfloat16(v.w));
}

__device__ __forceinline__ void load_chunk(uint32_t sb, int stage, int m0, int n0,
                                           int chunk, int tid) {
    const char* eb = reinterpret_cast<const char*>(g_Ebf);
    uint32_t sbase = sb + stage * STAGE_BYTES;
    size_t colb = (size_t)chunk * 128;  // byte offset of K-chunk within a 2048B row
#pragma unroll
    for (int q = 0; q < 4; q++) {
        int idx = tid + q * 256;        // 0..1023
        int row = idx >> 3;             // 0..127
        int c16 = idx & 7;              // 16B column within 128B row
        uint32_t sw = row * 128 + ((c16 * 16) ^ ((row & 7) << 4));
        size_t gA = (size_t)(m0 + row) * 2048 + colb + c16 * 16;
        size_t gB = (size_t)(n0 + row) * 2048 + colb + c16 * 16;
        cp_async16(sbase + sw, eb + gA);
        cp_async16(sbase + OFF_B + sw, eb + gB);
    }
}

__global__ void __launch_bounds__(256, 2)
sim_kernel(const long long* __restrict__ labels) {
    const int bi = blockIdx.y, bj = blockIdx.x;
    if (bi > bj) return;
    extern __shared__ char smem[];
    const uint32_t sb = smem_u32(smem);
    const int tid = threadIdx.x;
    const int wid = tid >> 5, lane = tid & 31;
    const int m0 = bi * TM, n0 = bj * TN;
    const bool diagTile = (bi == bj);

    int*   lAs = reinterpret_cast<int*>(smem + SM_LA);
    int*   lBs = reinterpret_cast<int*>(smem + SM_LB);
    float* rS = reinterpret_cast<float*>(smem + SM_RS);
    float* rP = reinterpret_cast<float*>(smem + SM_RP);
    int*   rC = reinterpret_cast<int*>(smem + SM_RC);
    float* cS = reinterpret_cast<float*>(smem + SM_CS);
    float* cP = reinterpret_cast<float*>(smem + SM_CP);
    int*   cC = reinterpret_cast<int*>(smem + SM_CC);

    if (tid < 128) {
        lAs[tid] = (int)labels[m0 + tid];
        lBs[tid] = (int)labels[n0 + tid];
        rS[tid] = 0.f; rP[tid] = 0.f; rC[tid] = 0;
        cS[tid] = 0.f; cP[tid] = 0.f; cC[tid] = 0;
    }

    // warp tiling: 4 warp-rows x 2 warp-cols; warp = 32 rows x 64 cols
    const int wr = wid & 3, wc = wid >> 2;
    const int qr = lane >> 2, qc = lane & 3;
    const uint32_t xmask = (lane & 7) << 4;
    const uint32_t rsel = lane & 15;
    const uint32_t csel = (lane >> 4) << 4;
    const uint32_t a_row0 = (wr * 32 + rsel) * 128;
    uint32_t b_row[4];
#pragma unroll
    for (int g = 0; g < 4; g++) b_row[g] = (wc * 64 + g * 16 + rsel) * 128;

    float acc[2][8][4];
#pragma unroll
    for (int i = 0; i < 2; i++)
#pragma unroll
        for (int j = 0; j < 8; j++)
#pragma unroll
            for (int k = 0; k < 4; k++) acc[i][j][k] = 0.f;

    load_chunk(sb, 0, m0, n0, 0, tid); cp_commit();
    load_chunk(sb, 1, m0, n0, 1, tid); cp_commit();

    for (int t = 0; t < NCHUNK; t++) {
        const int s = t & 1;
        if (t < NCHUNK - 1) asm volatile("cp.async.wait_group 1;" ::: "memory");
        else                asm volatile("cp.async.wait_group 0;" ::: "memory");
        __syncthreads();

        const uint32_t stg = sb + s * STAGE_BYTES;
#pragma unroll
        for (int ks = 0; ks < 4; ks++) {
            const uint32_t co = (ks * 32 + csel) ^ xmask;
            uint32_t a0[4], a1[4], bf[4][4];
            ldsm4(stg + a_row0 + co, a0[0], a0[1], a0[2], a0[3]);
            ldsm4(stg + a_row0 + 2048 + co, a1[0], a1[1], a1[2], a1[3]);
#pragma unroll
            for (int g = 0; g < 4; g++)
                ldsm4(stg + OFF_B + b_row[g] + co, bf[g][0], bf[g][1], bf[g][2], bf[g][3]);
#pragma unroll
            for (int j = 0; j < 8; j++) {
                const uint32_t bb0 = bf[j >> 1][j & 1];
                const uint32_t bb1 = bf[j >> 1][(j & 1) + 2];
                mma16816(acc[0][j], a0, bb0, bb1);
                mma16816(acc[1][j], a1, bb0, bb1);
            }
        }
        __syncthreads();
        if (t + 2 < NCHUNK) { load_chunk(sb, s, m0, n0, t + 2, tid); cp_commit(); }
    }

    // ---- fused epilogue (accumulators in registers) ----
    // thread covers rows: wr*32 + i*16 + h*8 + qr  (i,h in {0,1})
    //          and cols: wc*64 + j*8 + qc*2 + cc   (j in 0..7, cc in {0,1})
    int rowl[4], la[4];
#pragma unroll
    for (int i = 0; i < 2; i++)
#pragma unroll
        for (int h = 0; h < 2; h++) {
            int ri = i * 2 + h;
            rowl[ri] = wr * 32 + i * 16 + h * 8 + qr;
            la[ri] = lAs[rowl[ri]];
        }
    float rs[4] = {0, 0, 0, 0}, rp[4] = {0, 0, 0, 0};
    int   rc[4] = {0, 0, 0, 0};

#pragma unroll
    for (int j = 0; j < 8; j++) {
#pragma unroll
        for (int cc = 0; cc < 2; cc++) {
            const int lc = wc * 64 + j * 8 + qc * 2 + cc;
            const int lb = lBs[lc];
            float cs = 0.f, cp = 0.f; int cct = 0;
#pragma unroll
            for (int i = 0; i < 2; i++)
#pragma unroll
                for (int h = 0; h < 2; h++) {
                    const int ri = i * 2 + h;
                    const float simv = acc[i][j][h * 2 + cc] * INV_TAU;
                    const float e = fast_exp(simv);
                    const bool diag = diagTile && (rowl[ri] == lc);
                    if (!diag) {
                        rs[ri] += e;
                        const bool pos = (lb == la[ri]);
                        if (pos) { rp[ri] += simv; rc[ri]++; }
                        cs += e;
                        if (pos) { cp += simv; cct++; }
                    }
                }
            if (!diagTile) {
                atomicAdd(&cS[lc], cs);
                atomicAdd(&cP[lc], cp);
                atomicAdd(&cC[lc], cct);
            }
        }
    }
#pragma unroll
    for (int ri = 0; ri < 4; ri++) {
        atomicAdd(&rS[rowl[ri]], rs[ri]);
        atomicAdd(&rP[rowl[ri]], rp[ri]);
        atomicAdd(&rC[rowl[ri]], rc[ri]);
    }
    __syncthreads();

    if (tid < 128) {
        atomicAdd(&g_S[m0 + tid], rS[tid]);
        atomicAdd(&g_P[m0 + tid], rP[tid]);
        atomicAdd(&g_C[m0 + tid], rC[tid]);
        if (!diagTile) {
            atomicAdd(&g_S[n0 + tid], cS[tid]);
            atomicAdd(&g_P[n0 + tid], cP[tid]);
            atomicAdd(&g_C[n0 + tid], cC[tid]);
        }
    }
}

__global__ void final_reduce_kernel(float* __restrict__ out, int B) {
    __shared__ float sLoss[256];
    __shared__ int   sCnt[256];
    const int tid = threadIdx.x;
    float loss = 0.0f; int cnt = 0;
    for (int i = tid; i < B; i += 256) {
        const int c = g_C[i];
        if (c > 0) {
            loss += logf(g_S[i]) - g_P[i] / (float)c;
            cnt++;
        }
    }
    sLoss[tid] = loss; sCnt[tid] = cnt;
    __syncthreads();
    for (int s = 128; s > 0; s >>= 1) {
        if (tid < s) { sLoss[tid] += sLoss[tid + s]; sCnt[tid] += sCnt[tid + s]; }
        __syncthreads();
    }
    if (tid == 0) {
        int na = sCnt[0] > 0 ? sCnt[0] : 1;
        out[0] = sLoss[0] / (float)na;
    }
}

// ---------------- launch ----------------
extern "C" void kernel_launch(void* const* d_in, const int* in_sizes, int n_in,
                              void* d_out, int out_size) {
    const float*     E      = (const float*)d_in[0];
    const long long* labels = (const long long*)d_in[1];
    float*           out    = (float*)d_out;

    const int B = in_sizes[1];

    cudaFuncSetAttribute(sim_kernel, cudaFuncAttributeMaxDynamicSharedMemorySize, SMEM_TOTAL);

    zero_stats_kernel<<<(B + 255) / 256, 256>>>(B);
    convert_kernel<<<(B_SIZE * D_SIZE / 4) / 256, 256>>>(E);

    dim3 grid(B_SIZE / TN, B_SIZE / TM);
    sim_kernel<<<grid, 256, SMEM_TOTAL>>>(labels);

    final_reduce_kernel<<<1, 256>>>(out, B);
}

// round 4
// speedup vs baseline: 9.4537x; 1.0621x over previous
#include <cuda_runtime.h>
#include <cuda_bf16.h>
#include <cstdint>

#define B_SIZE 8192
#define D_SIZE 1024
#define TM 128
#define TN 128
#define KC 64                      // bf16 elems per K-chunk (128 bytes/row)
#define NCHUNK (D_SIZE / KC)       // 16
#define NSTAGE 3
#define INV_TAU 10.0f

// ---------------- device scratch (no allocations allowed) ----------------
__device__ float g_S[B_SIZE];
__device__ float g_P[B_SIZE];
__device__ int   g_C[B_SIZE];
__device__ float g_pl;             // partial loss
__device__ int   g_pc;             // partial anchor count
__device__ int   g_ticket;
__device__ __align__(16) __nv_bfloat16 g_Ebf[B_SIZE * D_SIZE];

// ---------------- smem layout ----------------
#define STAGE_BYTES 32768          // A tile 16KB + B tile 16KB
#define OFF_B 16384
#define SM_MISC (NSTAGE * STAGE_BYTES)
#define SM_LA  (SM_MISC + 0)       // int[128]
#define SM_LB  (SM_MISC + 512)
#define SM_RS  (SM_MISC + 1024)    // float[128]
#define SM_RP  (SM_MISC + 1536)
#define SM_RC  (SM_MISC + 2048)
#define SM_CS  (SM_MISC + 2560)
#define SM_CP  (SM_MISC + 3072)
#define SM_CC  (SM_MISC + 3584)
#define SMEM_TOTAL (SM_MISC + 4096)

// ---------------- helpers ----------------
__device__ __forceinline__ uint32_t smem_u32(const void* p) {
    uint32_t a;
    asm("{ .reg .u64 t; cvta.to.shared.u64 t, %1; cvt.u32.u64 %0, t; }" : "=r"(a) : "l"(p));
    return a;
}
__device__ __forceinline__ void cp_async16(uint32_t dst, const void* src) {
    asm volatile("cp.async.cg.shared.global [%0], [%1], 16;" :: "r"(dst), "l"(src));
}
__device__ __forceinline__ void cp_commit() { asm volatile("cp.async.commit_group;"); }

__device__ __forceinline__ void ldsm4(uint32_t addr, uint32_t& r0, uint32_t& r1,
                                      uint32_t& r2, uint32_t& r3) {
    asm volatile("ldmatrix.sync.aligned.m8n8.x4.shared.b16 {%0,%1,%2,%3}, [%4];"
                 : "=r"(r0), "=r"(r1), "=r"(r2), "=r"(r3) : "r"(addr));
}
__device__ __forceinline__ void mma16816(float* d, const uint32_t* a,
                                         uint32_t b0, uint32_t b1) {
    asm volatile(
        "mma.sync.aligned.m16n8k16.row.col.f32.bf16.bf16.f32 "
        "{%0,%1,%2,%3}, {%4,%5,%6,%7}, {%8,%9}, {%0,%1,%2,%3};"
        : "+f"(d[0]), "+f"(d[1]), "+f"(d[2]), "+f"(d[3])
        : "r"(a[0]), "r"(a[1]), "r"(a[2]), "r"(a[3]), "r"(b0), "r"(b1));
}

// fast e^x via 2^(x*log2e), degree-5 poly; valid for |x| <= ~14
__device__ __forceinline__ float fast_exp(float x) {
    const float LOG2E = 1.4426950408889634f;
    const float MAGIC = 12582912.0f;  // 1.5 * 2^23
    float y = x * LOG2E;
    float t = y + MAGIC;
    int   i = __float_as_int(t) - 0x4B400000;
    float f = y - (t - MAGIC);
    float p = 1.3333558e-3f;
    p = fmaf(p, f, 9.6181291e-3f);
    p = fmaf(p, f, 5.5504109e-2f);
    p = fmaf(p, f, 2.4022650e-1f);
    p = fmaf(p, f, 6.9314718e-1f);
    p = fmaf(p, f, 1.0f);
    return __int_as_float(__float_as_int(p) + (i << 23));
}

// ---------------- kernels ----------------
// convert fp32 -> bf16, and zero the stats (blocks 0..31 cover 8192 rows)
__global__ void convert_kernel(const float* __restrict__ E) {
    int idx = blockIdx.x * 256 + threadIdx.x;  // one float4 per thread
    if (idx < B_SIZE) { g_S[idx] = 0.f; g_P[idx] = 0.f; g_C[idx] = 0; }
    if (idx == 0) { g_pl = 0.f; g_pc = 0; g_ticket = 0; }
    float4 v = reinterpret_cast<const float4*>(E)[idx];
    __nv_bfloat162* hp = reinterpret_cast<__nv_bfloat162*>(g_Ebf);
    hp[idx * 2 + 0] = __nv_bfloat162(__float2bfloat16(v.x), __float2bfloat16(v.y));
    hp[idx * 2 + 1] = __nv_bfloat162(__float2bfloat16(v.z), __float2bfloat16(v.w));
}

__device__ __forceinline__ void load_chunk(uint32_t sb, int stage, int m0, int n0,
                                           int chunk, int tid) {
    const char* eb = reinterpret_cast<const char*>(g_Ebf);
    uint32_t sbase = sb + stage * STAGE_BYTES;
    size_t colb = (size_t)chunk * 128;  // byte offset of K-chunk within a 2048B row
#pragma unroll
    for (int q = 0; q < 4; q++) {
        int idx = tid + q * 256;        // 0..1023
        int row = idx >> 3;             // 0..127
        int c16 = idx & 7;              // 16B column within 128B row
        uint32_t sw = row * 128 + ((c16 * 16) ^ ((row & 7) << 4));
        size_t gA = (size_t)(m0 + row) * 2048 + colb + c16 * 16;
        size_t gB = (size_t)(n0 + row) * 2048 + colb + c16 * 16;
        cp_async16(sbase + sw, eb + gA);
        cp_async16(sbase + OFF_B + sw, eb + gB);
    }
}

__global__ void __launch_bounds__(256, 2)
sim_kernel(const long long* __restrict__ labels) {
    const int bi = blockIdx.y, bj = blockIdx.x;
    if (bi > bj) return;
    extern __shared__ char smem[];
    const uint32_t sb = smem_u32(smem);
    const int tid = threadIdx.x;
    const int wid = tid >> 5, lane = tid & 31;
    const int m0 = bi * TM, n0 = bj * TN;
    const bool diagTile = (bi == bj);

    int*   lAs = reinterpret_cast<int*>(smem + SM_LA);
    int*   lBs = reinterpret_cast<int*>(smem + SM_LB);
    float* rS = reinterpret_cast<float*>(smem + SM_RS);
    float* rP = reinterpret_cast<float*>(smem + SM_RP);
    int*   rC = reinterpret_cast<int*>(smem + SM_RC);
    float* cS = reinterpret_cast<float*>(smem + SM_CS);
    float* cP = reinterpret_cast<float*>(smem + SM_CP);
    int*   cC = reinterpret_cast<int*>(smem + SM_CC);

    if (tid < 128) {
        lAs[tid] = (int)labels[m0 + tid];
        lBs[tid] = (int)labels[n0 + tid];
        rS[tid] = 0.f; rP[tid] = 0.f; rC[tid] = 0;
        cS[tid] = 0.f; cP[tid] = 0.f; cC[tid] = 0;
    }

    // warp tiling: 4 warp-rows x 2 warp-cols; warp = 32 rows x 64 cols
    const int wr = wid & 3, wc = wid >> 2;
    const int qr = lane >> 2, qc = lane & 3;
    const uint32_t xmask = (lane & 7) << 4;
    const uint32_t rsel = lane & 15;
    const uint32_t csel = (lane >> 4) << 4;
    const uint32_t a_row0 = (wr * 32 + rsel) * 128;
    uint32_t b_row[4];
#pragma unroll
    for (int g = 0; g < 4; g++) b_row[g] = (wc * 64 + g * 16 + rsel) * 128;

    float acc[2][8][4];
#pragma unroll
    for (int i = 0; i < 2; i++)
#pragma unroll
        for (int j = 0; j < 8; j++)
#pragma unroll
            for (int k = 0; k < 4; k++) acc[i][j][k] = 0.f;

    load_chunk(sb, 0, m0, n0, 0, tid); cp_commit();
    load_chunk(sb, 1, m0, n0, 1, tid); cp_commit();

    for (int t = 0; t < NCHUNK; t++) {
        if (t < NCHUNK - 1) asm volatile("cp.async.wait_group 1;" ::: "memory");
        else                asm volatile("cp.async.wait_group 0;" ::: "memory");
        __syncthreads();

        // prefetch chunk t+2 into stage (t+2)%3 == (t-1)%3 (free: all warps
        // passed the barrier above, so compute(t-1) reads are complete).
        if (t + 2 < NCHUNK) {
            int ps = t + 2 - NSTAGE * ((t + 2) / NSTAGE);
            load_chunk(sb, ps, m0, n0, t + 2, tid);
            cp_commit();
        }

        const uint32_t stg = sb + (t - NSTAGE * (t / NSTAGE)) * STAGE_BYTES;
#pragma unroll
        for (int ks = 0; ks < 4; ks++) {
            const uint32_t co = (ks * 32 + csel) ^ xmask;
            uint32_t a0[4], a1[4], bf[4][4];
            ldsm4(stg + a_row0 + co, a0[0], a0[1], a0[2], a0[3]);
            ldsm4(stg + a_row0 + 2048 + co, a1[0], a1[1], a1[2], a1[3]);
#pragma unroll
            for (int g = 0; g < 4; g++)
                ldsm4(stg + OFF_B + b_row[g] + co, bf[g][0], bf[g][1], bf[g][2], bf[g][3]);
#pragma unroll
            for (int j = 0; j < 8; j++) {
                const uint32_t bb0 = bf[j >> 1][j & 1];
                const uint32_t bb1 = bf[j >> 1][(j & 1) + 2];
                mma16816(acc[0][j], a0, bb0, bb1);
                mma16816(acc[1][j], a1, bb0, bb1);
            }
        }
    }

    // ---- fused epilogue (accumulators in registers) ----
    int rowl[4], la[4];
#pragma unroll
    for (int i = 0; i < 2; i++)
#pragma unroll
        for (int h = 0; h < 2; h++) {
            int ri = i * 2 + h;
            rowl[ri] = wr * 32 + i * 16 + h * 8 + qr;
            la[ri] = lAs[rowl[ri]];
        }
    float rs[4] = {0, 0, 0, 0}, rp[4] = {0, 0, 0, 0};
    int   rc[4] = {0, 0, 0, 0};

#pragma unroll
    for (int j = 0; j < 8; j++) {
#pragma unroll
        for (int cc = 0; cc < 2; cc++) {
            const int lc = wc * 64 + j * 8 + qc * 2 + cc;
            const int lb = lBs[lc];
            float cs = 0.f, cp = 0.f; int cct = 0;
#pragma unroll
            for (int i = 0; i < 2; i++)
#pragma unroll
                for (int h = 0; h < 2; h++) {
                    const int ri = i * 2 + h;
                    const float simv = acc[i][j][h * 2 + cc] * INV_TAU;
                    const float e = fast_exp(simv);
                    const bool diag = diagTile && (rowl[ri] == lc);
                    if (!diag) {
                        rs[ri] += e;
                        const bool pos = (lb == la[ri]);
                        if (pos) { rp[ri] += simv; rc[ri]++; }
                        cs += e;
                        if (pos) { cp += simv; cct++; }
                    }
                }
            if (!diagTile) {
                atomicAdd(&cS[lc], cs);
                atomicAdd(&cP[lc], cp);
                atomicAdd(&cC[lc], cct);
            }
        }
    }
#pragma unroll
    for (int ri = 0; ri < 4; ri++) {
        atomicAdd(&rS[rowl[ri]], rs[ri]);
        atomicAdd(&rP[rowl[ri]], rp[ri]);
        atomicAdd(&rC[rowl[ri]], rc[ri]);
    }
    __syncthreads();

    if (tid < 128) {
        atomicAdd(&g_S[m0 + tid], rS[tid]);
        atomicAdd(&g_P[m0 + tid], rP[tid]);
        atomicAdd(&g_C[m0 + tid], rC[tid]);
        if (!diagTile) {
            atomicAdd(&g_S[n0 + tid], cS[tid]);
            atomicAdd(&g_P[n0 + tid], cP[tid]);
            atomicAdd(&g_C[n0 + tid], cC[tid]);
        }
    }
}

// 64 blocks x 128 threads; last block finalizes via ticket.
__global__ void reduce_kernel(float* __restrict__ out) {
    const int tid = threadIdx.x;
    const int r = blockIdx.x * 128 + tid;
    float loss = 0.f; int cnt = 0;
    const int c = g_C[r];
    if (c > 0) { loss = logf(g_S[r]) - g_P[r] / (float)c; cnt = 1; }
#pragma unroll
    for (int o = 16; o > 0; o >>= 1) {
        loss += __shfl_down_sync(0xFFFFFFFFu, loss, o);
        cnt  += __shfl_down_sync(0xFFFFFFFFu, cnt, o);
    }
    __shared__ float sl[4];
    __shared__ int   sc[4];
    if ((tid & 31) == 0) { sl[tid >> 5] = loss; sc[tid >> 5] = cnt; }
    __syncthreads();
    if (tid == 0) {
        float L = sl[0] + sl[1] + sl[2] + sl[3];
        int   C = sc[0] + sc[1] + sc[2] + sc[3];
        atomicAdd(&g_pl, L);
        atomicAdd(&g_pc, C);
        __threadfence();
        int prev = atomicAdd(&g_ticket, 1);
        if (prev == 63) {
            float tl = atomicAdd(&g_pl, 0.f);
            int   tc = atomicAdd(&g_pc, 0);
            out[0] = tl / (float)(tc > 0 ? tc : 1);
        }
    }
}

// ---------------- launch ----------------
extern "C" void kernel_launch(void* const* d_in, const int* in_sizes, int n_in,
                              void* d_out, int out_size) {
    const float*     E      = (const float*)d_in[0];
    const long long* labels = (const long long*)d_in[1];
    float*           out    = (float*)d_out;

    cudaFuncSetAttribute(sim_kernel, cudaFuncAttributeMaxDynamicSharedMemorySize, SMEM_TOTAL);

    convert_kernel<<<(B_SIZE * D_SIZE / 4) / 256, 256>>>(E);

    dim3 grid(B_SIZE / TN, B_SIZE / TM);
    sim_kernel<<<grid, 256, SMEM_TOTAL>>>(labels);

    reduce_kernel<<<64, 128>>>(out);
}

// round 5
// speedup vs baseline: 12.0757x; 1.2774x over previous
#include <cuda_runtime.h>
#include <cuda_bf16.h>
#include <cstdint>

#define B_SIZE 8192
#define D_SIZE 1024
#define TM 128
#define TN 128
#define KC 64                      // bf16 elems per K-chunk (128 bytes/row)
#define NCHUNK (D_SIZE / KC)       // 16
#define NSTAGE 3
#define INV_TAU 10.0f

// ---------------- device scratch (no allocations allowed) ----------------
__device__ float g_S[B_SIZE];
__device__ float g_P[B_SIZE];
__device__ int   g_C[B_SIZE];
__device__ float g_pl;
__device__ int   g_pc;
__device__ int   g_ticket;
__device__ __align__(16) __nv_bfloat16 g_Ebf[B_SIZE * D_SIZE];

// ---------------- smem layout ----------------
#define STAGE_BYTES 32768          // A tile 16KB + B tile 16KB
#define OFF_B 16384
#define SM_MISC (NSTAGE * STAGE_BYTES)
#define SM_LA  (SM_MISC + 0)       // int[128]
#define SM_LB  (SM_MISC + 512)
#define SM_RS  (SM_MISC + 1024)    // float[128]
#define SM_RP  (SM_MISC + 1536)
#define SM_RC  (SM_MISC + 2048)
#define SM_CS  (SM_MISC + 2560)
#define SM_CP  (SM_MISC + 3072)
#define SM_CC  (SM_MISC + 3584)
#define SMEM_TOTAL (SM_MISC + 4096)

// ---------------- helpers ----------------
__device__ __forceinline__ uint32_t smem_u32(const void* p) {
    uint32_t a;
    asm("{ .reg .u64 t; cvta.to.shared.u64 t, %1; cvt.u32.u64 %0, t; }" : "=r"(a) : "l"(p));
    return a;
}
__device__ __forceinline__ void cp_async16(uint32_t dst, const void* src) {
    asm volatile("cp.async.cg.shared.global [%0], [%1], 16;" :: "r"(dst), "l"(src));
}
__device__ __forceinline__ void cp_commit() { asm volatile("cp.async.commit_group;"); }

__device__ __forceinline__ void ldsm4(uint32_t addr, uint32_t* r) {
    asm volatile("ldmatrix.sync.aligned.m8n8.x4.shared.b16 {%0,%1,%2,%3}, [%4];"
                 : "=r"(r[0]), "=r"(r[1]), "=r"(r[2]), "=r"(r[3]) : "r"(addr));
}
__device__ __forceinline__ void mma16816(float* d, const uint32_t* a,
                                         uint32_t b0, uint32_t b1) {
    asm volatile(
        "mma.sync.aligned.m16n8k16.row.col.f32.bf16.bf16.f32 "
        "{%0,%1,%2,%3}, {%4,%5,%6,%7}, {%8,%9}, {%0,%1,%2,%3};"
        : "+f"(d[0]), "+f"(d[1]), "+f"(d[2]), "+f"(d[3])
        : "r"(a[0]), "r"(a[1]), "r"(a[2]), "r"(a[3]), "r"(b0), "r"(b1));
}

// fast e^x via 2^(x*log2e), degree-5 poly; valid for |x| <= ~14
__device__ __forceinline__ float fast_exp(float x) {
    const float LOG2E = 1.4426950408889634f;
    const float MAGIC = 12582912.0f;  // 1.5 * 2^23
    float y = x * LOG2E;
    float t = y + MAGIC;
    int   i = __float_as_int(t) - 0x4B400000;
    float f = y - (t - MAGIC);
    float p = 1.3333558e-3f;
    p = fmaf(p, f, 9.6181291e-3f);
    p = fmaf(p, f, 5.5504109e-2f);
    p = fmaf(p, f, 2.4022650e-1f);
    p = fmaf(p, f, 6.9314718e-1f);
    p = fmaf(p, f, 1.0f);
    return __int_as_float(__float_as_int(p) + (i << 23));
}

// ---------------- kernels ----------------
__global__ void convert_kernel(const float* __restrict__ E) {
    int idx = blockIdx.x * 256 + threadIdx.x;  // one float4 per thread
    if (idx < B_SIZE) { g_S[idx] = 0.f; g_P[idx] = 0.f; g_C[idx] = 0; }
    if (idx == 0) { g_pl = 0.f; g_pc = 0; g_ticket = 0; }
    float4 v = reinterpret_cast<const float4*>(E)[idx];
    __nv_bfloat162* hp = reinterpret_cast<__nv_bfloat162*>(g_Ebf);
    hp[idx * 2 + 0] = __nv_bfloat162(__float2bfloat16(v.x), __float2bfloat16(v.y));
    hp[idx * 2 + 1] = __nv_bfloat162(__float2bfloat16(v.z), __float2bfloat16(v.w));
}

__device__ __forceinline__ void load_chunk(uint32_t sb, int stage, int m0, int n0,
                                           int chunk, int tid) {
    const char* eb = reinterpret_cast<const char*>(g_Ebf);
    uint32_t sbase = sb + stage * STAGE_BYTES;
    size_t colb = (size_t)chunk * 128;
#pragma unroll
    for (int q = 0; q < 8; q++) {
        int idx = tid + q * 128;        // 0..1023
        int row = idx >> 3;             // 0..127
        int c16 = idx & 7;
        uint32_t sw = row * 128 + ((c16 * 16) ^ ((row & 7) << 4));
        size_t gA = (size_t)(m0 + row) * 2048 + colb + c16 * 16;
        size_t gB = (size_t)(n0 + row) * 2048 + colb + c16 * 16;
        cp_async16(sbase + sw, eb + gA);
        cp_async16(sbase + OFF_B + sw, eb + gB);
    }
}

__global__ void __launch_bounds__(128, 2)
sim_kernel(const long long* __restrict__ labels) {
    const int bi = blockIdx.y, bj = blockIdx.x;
    if (bi > bj) return;
    extern __shared__ char smem[];
    const uint32_t sb = smem_u32(smem);
    const int tid = threadIdx.x;
    const int wid = tid >> 5, lane = tid & 31;
    const int m0 = bi * TM, n0 = bj * TN;
    const bool diagTile = (bi == bj);

    int*   lAs = reinterpret_cast<int*>(smem + SM_LA);
    int*   lBs = reinterpret_cast<int*>(smem + SM_LB);
    float* rS = reinterpret_cast<float*>(smem + SM_RS);
    float* rP = reinterpret_cast<float*>(smem + SM_RP);
    int*   rC = reinterpret_cast<int*>(smem + SM_RC);
    float* cS = reinterpret_cast<float*>(smem + SM_CS);
    float* cP = reinterpret_cast<float*>(smem + SM_CP);
    int*   cC = reinterpret_cast<int*>(smem + SM_CC);

    if (tid < 128) {
        lAs[tid] = (int)labels[m0 + tid];
        lBs[tid] = (int)labels[n0 + tid];
        rS[tid] = 0.f; rP[tid] = 0.f; rC[tid] = 0;
        cS[tid] = 0.f; cP[tid] = 0.f; cC[tid] = 0;
    }

    // 4 warps, 2x2; warp tile = 64 rows x 64 cols
    const int wr = wid >> 1, wc = wid & 1;
    const int qr = lane >> 2, qc = lane & 3;
    const uint32_t xmask = (lane & 7) << 4;
    const uint32_t rsel = lane & 15;
    const uint32_t csel = (lane >> 4) << 4;
    uint32_t a_row[4], b_row[4];
#pragma unroll
    for (int g = 0; g < 4; g++) {
        a_row[g] = (wr * 64 + g * 16 + rsel) * 128;
        b_row[g] = (wc * 64 + g * 16 + rsel) * 128;
    }

    float acc[4][8][4];
#pragma unroll
    for (int i = 0; i < 4; i++)
#pragma unroll
        for (int j = 0; j < 8; j++)
#pragma unroll
            for (int k = 0; k < 4; k++) acc[i][j][k] = 0.f;

    load_chunk(sb, 0, m0, n0, 0, tid); cp_commit();
    load_chunk(sb, 1, m0, n0, 1, tid); cp_commit();

    for (int t = 0; t < NCHUNK; t++) {
        if (t < NCHUNK - 1) asm volatile("cp.async.wait_group 1;" ::: "memory");
        else                asm volatile("cp.async.wait_group 0;" ::: "memory");
        __syncthreads();

        if (t + 2 < NCHUNK) {
            int ps = t + 2 - NSTAGE * ((t + 2) / NSTAGE);
            load_chunk(sb, ps, m0, n0, t + 2, tid);
            cp_commit();
        }

        const uint32_t stg = sb + (t - NSTAGE * (t / NSTAGE)) * STAGE_BYTES;
#pragma unroll
        for (int ks = 0; ks < 4; ks++) {
            const uint32_t co = (ks * 32 + csel) ^ xmask;
            uint32_t a[4][4], b[4][4];
#pragma unroll
            for (int g = 0; g < 4; g++) ldsm4(stg + a_row[g] + co, a[g]);
#pragma unroll
            for (int g = 0; g < 4; g++) ldsm4(stg + OFF_B + b_row[g] + co, b[g]);
#pragma unroll
            for (int i = 0; i < 4; i++)
#pragma unroll
                for (int j = 0; j < 8; j++)
                    mma16816(acc[i][j], a[i], b[j >> 1][j & 1], b[j >> 1][(j & 1) + 2]);
        }
    }

    // ---- fused epilogue ----
    int rowl[8], la[8];
#pragma unroll
    for (int i = 0; i < 4; i++)
#pragma unroll
        for (int h = 0; h < 2; h++) {
            int ri = i * 2 + h;
            rowl[ri] = wr * 64 + i * 16 + h * 8 + qr;
            la[ri] = lAs[rowl[ri]];
        }
    float rs[8], rp[8]; int rc[8];
#pragma unroll
    for (int ri = 0; ri < 8; ri++) { rs[ri] = 0.f; rp[ri] = 0.f; rc[ri] = 0; }

#pragma unroll
    for (int j = 0; j < 8; j++) {
#pragma unroll
        for (int cc = 0; cc < 2; cc++) {
            const int lc = wc * 64 + j * 8 + qc * 2 + cc;
            const int lb = lBs[lc];
            float cs = 0.f, cp = 0.f; int cct = 0;
#pragma unroll
            for (int i = 0; i < 4; i++)
#pragma unroll
                for (int h = 0; h < 2; h++) {
                    const int ri = i * 2 + h;
                    const float simv = acc[i][j][h * 2 + cc] * INV_TAU;
                    const float e = fast_exp(simv);
                    const bool diag = diagTile && (rowl[ri] == lc);
                    if (!diag) {
                        rs[ri] += e;
                        const bool pos = (lb == la[ri]);
                        if (pos) { rp[ri] += simv; rc[ri]++; }
                        cs += e;
                        if (pos) { cp += simv; cct++; }
                    }
                }
            if (!diagTile) {
                // reduce across qr lanes (stride 4): 8 partials -> 1
#pragma unroll
                for (int o = 4; o <= 16; o <<= 1) {
                    cs  += __shfl_xor_sync(0xFFFFFFFFu, cs, o);
                    cp  += __shfl_xor_sync(0xFFFFFFFFu, cp, o);
                    cct += __shfl_xor_sync(0xFFFFFFFFu, cct, o);
                }
                if (qr == 0) {
                    atomicAdd(&cS[lc], cs);
                    atomicAdd(&cP[lc], cp);
                    atomicAdd(&cC[lc], cct);
                }
            }
        }
    }
    // reduce row stats across qc lanes (stride 1): 4 partials -> 1
#pragma unroll
    for (int ri = 0; ri < 8; ri++) {
#pragma unroll
        for (int o = 1; o <= 2; o <<= 1) {
            rs[ri] += __shfl_xor_sync(0xFFFFFFFFu, rs[ri], o);
            rp[ri] += __shfl_xor_sync(0xFFFFFFFFu, rp[ri], o);
            rc[ri] += __shfl_xor_sync(0xFFFFFFFFu, rc[ri], o);
        }
        if (qc == 0) {
            atomicAdd(&rS[rowl[ri]], rs[ri]);
            atomicAdd(&rP[rowl[ri]], rp[ri]);
            atomicAdd(&rC[rowl[ri]], rc[ri]);
        }
    }
    __syncthreads();

    if (tid < 128) {
        atomicAdd(&g_S[m0 + tid], rS[tid]);
        atomicAdd(&g_P[m0 + tid], rP[tid]);
        atomicAdd(&g_C[m0 + tid], rC[tid]);
        if (!diagTile) {
            atomicAdd(&g_S[n0 + tid], cS[tid]);
            atomicAdd(&g_P[n0 + tid], cP[tid]);
            atomicAdd(&g_C[n0 + tid], cC[tid]);
        }
    }
}

// 64 blocks x 128 threads; last block finalizes via ticket.
__global__ void reduce_kernel(float* __restrict__ out) {
    const int tid = threadIdx.x;
    const int r = blockIdx.x * 128 + tid;
    float loss = 0.f; int cnt = 0;
    const int c = g_C[r];
    if (c > 0) { loss = logf(g_S[r]) - g_P[r] / (float)c; cnt = 1; }
#pragma unroll
    for (int o = 16; o > 0; o >>= 1) {
        loss += __shfl_down_sync(0xFFFFFFFFu, loss, o);
        cnt  += __shfl_down_sync(0xFFFFFFFFu, cnt, o);
    }
    __shared__ float sl[4];
    __shared__ int   sc[4];
    if ((tid & 31) == 0) { sl[tid >> 5] = loss; sc[tid >> 5] = cnt; }
    __syncthreads();
    if (tid == 0) {
        float L = sl[0] + sl[1] + sl[2] + sl[3];
        int   C = sc[0] + sc[1] + sc[2] + sc[3];
        atomicAdd(&g_pl, L);
        atomicAdd(&g_pc, C);
        __threadfence();
        int prev = atomicAdd(&g_ticket, 1);
        if (prev == 63) {
            float tl = atomicAdd(&g_pl, 0.f);
            int   tc = atomicAdd(&g_pc, 0);
            out[0] = tl / (float)(tc > 0 ? tc : 1);
        }
    }
}

// ---------------- launch ----------------
extern "C" void kernel_launch(void* const* d_in, const int* in_sizes, int n_in,
                              void* d_out, int out_size) {
    const float*     E      = (const float*)d_in[0];
    const long long* labels = (const long long*)d_in[1];
    float*           out    = (float*)d_out;

    cudaFuncSetAttribute(sim_kernel, cudaFuncAttributeMaxDynamicSharedMemorySize, SMEM_TOTAL);

    convert_kernel<<<(B_SIZE * D_SIZE / 4) / 256, 256>>>(E);

    dim3 grid(B_SIZE / TN, B_SIZE / TM);
    sim_kernel<<<grid, 128, SMEM_TOTAL>>>(labels);

    reduce_kernel<<<64, 128>>>(out);
}

// round 6
// speedup vs baseline: 12.7181x; 1.0532x over previous
#include <cuda_runtime.h>
#include <cuda_bf16.h>
#include <cstdint>

#define B_SIZE 8192
#define D_SIZE 1024
#define TM 128
#define TN 128
#define KC 64                      // bf16 elems per K-chunk (128 bytes/row)
#define NCHUNK (D_SIZE / KC)       // 16
#define NSTAGE 3
#define INV_TAU 10.0f

// ---------------- device scratch (no allocations allowed) ----------------
__device__ float g_S[B_SIZE];
__device__ float g_P[B_SIZE];
__device__ int   g_C[B_SIZE];
__device__ float g_pl;
__device__ int   g_pc;
__device__ int   g_ticket;
__device__ __align__(16) __nv_bfloat16 g_Ebf[B_SIZE * D_SIZE];

// ---------------- smem layout ----------------
#define STAGE_BYTES 32768          // A tile 16KB + B tile 16KB
#define OFF_B 16384
#define SM_MISC (NSTAGE * STAGE_BYTES)
#define SM_LA  (SM_MISC + 0)       // int[128]
#define SM_LB  (SM_MISC + 512)
#define SM_RS  (SM_MISC + 1024)    // float[128]
#define SM_RP  (SM_MISC + 1536)
#define SM_RC  (SM_MISC + 2048)
#define SM_CS  (SM_MISC + 2560)
#define SM_CP  (SM_MISC + 3072)
#define SM_CC  (SM_MISC + 3584)
#define SMEM_TOTAL (SM_MISC + 4096)

// ---------------- helpers ----------------
__device__ __forceinline__ uint32_t smem_u32(const void* p) {
    uint32_t a;
    asm("{ .reg .u64 t; cvta.to.shared.u64 t, %1; cvt.u32.u64 %0, t; }" : "=r"(a) : "l"(p));
    return a;
}
__device__ __forceinline__ void cp_async16(uint32_t dst, const void* src) {
    asm volatile("cp.async.cg.shared.global [%0], [%1], 16;" :: "r"(dst), "l"(src));
}
__device__ __forceinline__ void cp_commit() { asm volatile("cp.async.commit_group;"); }

__device__ __forceinline__ void ldsm4(uint32_t addr, uint32_t* r) {
    asm volatile("ldmatrix.sync.aligned.m8n8.x4.shared.b16 {%0,%1,%2,%3}, [%4];"
                 : "=r"(r[0]), "=r"(r[1]), "=r"(r[2]), "=r"(r[3]) : "r"(addr));
}
__device__ __forceinline__ void mma16816(float* d, const uint32_t* a,
                                         uint32_t b0, uint32_t b1) {
    asm volatile(
        "mma.sync.aligned.m16n8k16.row.col.f32.bf16.bf16.f32 "
        "{%0,%1,%2,%3}, {%4,%5,%6,%7}, {%8,%9}, {%0,%1,%2,%3};"
        : "+f"(d[0]), "+f"(d[1]), "+f"(d[2]), "+f"(d[3])
        : "r"(a[0]), "r"(a[1]), "r"(a[2]), "r"(a[3]), "r"(b0), "r"(b1));
}

// fast e^x via 2^(x*log2e), degree-5 poly; valid for |x| <= ~14
__device__ __forceinline__ float fast_exp(float x) {
    const float LOG2E = 1.4426950408889634f;
    const float MAGIC = 12582912.0f;  // 1.5 * 2^23
    float y = x * LOG2E;
    float t = y + MAGIC;
    int   i = __float_as_int(t) - 0x4B400000;
    float f = y - (t - MAGIC);
    float p = 1.3333558e-3f;
    p = fmaf(p, f, 9.6181291e-3f);
    p = fmaf(p, f, 5.5504109e-2f);
    p = fmaf(p, f, 2.4022650e-1f);
    p = fmaf(p, f, 6.9314718e-1f);
    p = fmaf(p, f, 1.0f);
    return __int_as_float(__float_as_int(p) + (i << 23));
}

// ---------------- kernels ----------------
__global__ void convert_kernel(const float* __restrict__ E) {
    int idx = blockIdx.x * 256 + threadIdx.x;  // one float4 per thread
    if (idx < B_SIZE) { g_S[idx] = 0.f; g_P[idx] = 0.f; g_C[idx] = 0; }
    if (idx == 0) { g_pl = 0.f; g_pc = 0; g_ticket = 0; }
    float4 v = reinterpret_cast<const float4*>(E)[idx];
    __nv_bfloat162* hp = reinterpret_cast<__nv_bfloat162*>(g_Ebf);
    hp[idx * 2 + 0] = __nv_bfloat162(__float2bfloat16(v.x), __float2bfloat16(v.y));
    hp[idx * 2 + 1] = __nv_bfloat162(__float2bfloat16(v.z), __float2bfloat16(v.w));
}

__device__ __forceinline__ void load_chunk(uint32_t sb, int stage, int m0, int n0,
                                           int chunk, int tid) {
    const char* eb = reinterpret_cast<const char*>(g_Ebf);
    uint32_t sbase = sb + stage * STAGE_BYTES;
    size_t colb = (size_t)chunk * 128;
#pragma unroll
    for (int q = 0; q < 8; q++) {
        int idx = tid + q * 128;        // 0..1023
        int row = idx >> 3;             // 0..127
        int c16 = idx & 7;
        uint32_t sw = row * 128 + ((c16 * 16) ^ ((row & 7) << 4));
        size_t gA = (size_t)(m0 + row) * 2048 + colb + c16 * 16;
        size_t gB = (size_t)(n0 + row) * 2048 + colb + c16 * 16;
        cp_async16(sbase + sw, eb + gA);
        cp_async16(sbase + OFF_B + sw, eb + gB);
    }
}

__global__ void __launch_bounds__(128, 2)
sim_kernel(const long long* __restrict__ labels) {
    const int bi = blockIdx.y, bj = blockIdx.x;
    if (bi > bj) return;
    extern __shared__ char smem[];
    const uint32_t sb = smem_u32(smem);
    const int tid = threadIdx.x;
    const int wid = tid >> 5, lane = tid & 31;
    const int m0 = bi * TM, n0 = bj * TN;
    const bool diagTile = (bi == bj);

    int*   lAs = reinterpret_cast<int*>(smem + SM_LA);
    int*   lBs = reinterpret_cast<int*>(smem + SM_LB);
    float* rS = reinterpret_cast<float*>(smem + SM_RS);
    float* rP = reinterpret_cast<float*>(smem + SM_RP);
    int*   rC = reinterpret_cast<int*>(smem + SM_RC);
    float* cS = reinterpret_cast<float*>(smem + SM_CS);
    float* cP = reinterpret_cast<float*>(smem + SM_CP);
    int*   cC = reinterpret_cast<int*>(smem + SM_CC);

    if (tid < 128) {
        lAs[tid] = (int)labels[m0 + tid];
        lBs[tid] = (int)labels[n0 + tid];
        rS[tid] = 0.f; rP[tid] = 0.f; rC[tid] = 0;
        cS[tid] = 0.f; cP[tid] = 0.f; cC[tid] = 0;
    }

    // 4 warps, 2x2; warp tile = 64 rows x 64 cols
    const int wr = wid >> 1, wc = wid & 1;
    const int qr = lane >> 2, qc = lane & 3;
    const uint32_t xmask = (lane & 7) << 4;
    const uint32_t rsel = lane & 15;
    const uint32_t csel = (lane >> 4) << 4;
    uint32_t a_row[4], b_row[4];
#pragma unroll
    for (int g = 0; g < 4; g++) {
        a_row[g] = (wr * 64 + g * 16 + rsel) * 128;
        b_row[g] = (wc * 64 + g * 16 + rsel) * 128 + OFF_B;
    }

    float acc[4][8][4];
#pragma unroll
    for (int i = 0; i < 4; i++)
#pragma unroll
        for (int j = 0; j < 8; j++)
#pragma unroll
            for (int k = 0; k < 4; k++) acc[i][j][k] = 0.f;

    load_chunk(sb, 0, m0, n0, 0, tid); cp_commit();
    load_chunk(sb, 1, m0, n0, 1, tid); cp_commit();

    uint32_t a[2][4][4], b[2][4][4];   // register double buffer

    for (int t = 0; t < NCHUNK; t++) {
        if (t < NCHUNK - 1) asm volatile("cp.async.wait_group 1;" ::: "memory");
        else                asm volatile("cp.async.wait_group 0;" ::: "memory");
        __syncthreads();

        const uint32_t stg = sb + (t - NSTAGE * (t / NSTAGE)) * STAGE_BYTES;

        // preload ks=0 fragments
        {
            const uint32_t co = csel ^ xmask;
#pragma unroll
            for (int g = 0; g < 4; g++) ldsm4(stg + a_row[g] + co, a[0][g]);
#pragma unroll
            for (int g = 0; g < 4; g++) ldsm4(stg + b_row[g] + co, b[0][g]);
        }

        // prefetch chunk t+2 (overlaps with the HMMA work below)
        if (t + 2 < NCHUNK) {
            int ps = t + 2 - NSTAGE * ((t + 2) / NSTAGE);
            load_chunk(sb, ps, m0, n0, t + 2, tid);
            cp_commit();
        }

#pragma unroll
        for (int ks = 0; ks < 4; ks++) {
            const int cur = ks & 1, nxt = cur ^ 1;
            if (ks < 3) {
                const uint32_t co = ((ks + 1) * 32 + csel) ^ xmask;
#pragma unroll
                for (int g = 0; g < 4; g++) ldsm4(stg + a_row[g] + co, a[nxt][g]);
#pragma unroll
                for (int g = 0; g < 4; g++) ldsm4(stg + b_row[g] + co, b[nxt][g]);
            }
#pragma unroll
            for (int i = 0; i < 4; i++)
#pragma unroll
                for (int j = 0; j < 8; j++)
                    mma16816(acc[i][j], a[cur][i],
                             b[cur][j >> 1][j & 1], b[cur][j >> 1][(j & 1) + 2]);
        }
    }

    // ---- fused epilogue ----
    int rowl[8], la[8];
#pragma unroll
    for (int i = 0; i < 4; i++)
#pragma unroll
        for (int h = 0; h < 2; h++) {
            int ri = i * 2 + h;
            rowl[ri] = wr * 64 + i * 16 + h * 8 + qr;
            la[ri] = lAs[rowl[ri]];
        }
    float rs[8], rp[8]; int rc[8];
#pragma unroll
    for (int ri = 0; ri < 8; ri++) { rs[ri] = 0.f; rp[ri] = 0.f; rc[ri] = 0; }

#pragma unroll
    for (int j = 0; j < 8; j++) {
#pragma unroll
        for (int cc = 0; cc < 2; cc++) {
            const int lc = wc * 64 + j * 8 + qc * 2 + cc;
            const int lb = lBs[lc];
            float cs = 0.f, cp = 0.f; int cct = 0;
#pragma unroll
            for (int i = 0; i < 4; i++)
#pragma unroll
                for (int h = 0; h < 2; h++) {
                    const int ri = i * 2 + h;
                    const float simv = acc[i][j][h * 2 + cc] * INV_TAU;
                    const float e = fast_exp(simv);
                    const bool diag = diagTile && (rowl[ri] == lc);
                    if (!diag) {
                        rs[ri] += e;
                        const bool pos = (lb == la[ri]);
                        if (pos) { rp[ri] += simv; rc[ri]++; }
                        cs += e;
                        if (pos) { cp += simv; cct++; }
                    }
                }
            if (!diagTile) {
                // reduce across qr lanes (stride 4): 8 partials -> 1
#pragma unroll
                for (int o = 4; o <= 16; o <<= 1) {
                    cs  += __shfl_xor_sync(0xFFFFFFFFu, cs, o);
                    cp  += __shfl_xor_sync(0xFFFFFFFFu, cp, o);
                    cct += __shfl_xor_sync(0xFFFFFFFFu, cct, o);
                }
                if (qr == 0) {
                    atomicAdd(&cS[lc], cs);
                    atomicAdd(&cP[lc], cp);
                    atomicAdd(&cC[lc], cct);
                }
            }
        }
    }
    // reduce row stats across qc lanes (stride 1): 4 partials -> 1
#pragma unroll
    for (int ri = 0; ri < 8; ri++) {
#pragma unroll
        for (int o = 1; o <= 2; o <<= 1) {
            rs[ri] += __shfl_xor_sync(0xFFFFFFFFu, rs[ri], o);
            rp[ri] += __shfl_xor_sync(0xFFFFFFFFu, rp[ri], o);
            rc[ri] += __shfl_xor_sync(0xFFFFFFFFu, rc[ri], o);
        }
        if (qc == 0) {
            atomicAdd(&rS[rowl[ri]], rs[ri]);
            atomicAdd(&rP[rowl[ri]], rp[ri]);
            atomicAdd(&rC[rowl[ri]], rc[ri]);
        }
    }
    __syncthreads();

    if (tid < 128) {
        atomicAdd(&g_S[m0 + tid], rS[tid]);
        atomicAdd(&g_P[m0 + tid], rP[tid]);
        atomicAdd(&g_C[m0 + tid], rC[tid]);
        if (!diagTile) {
            atomicAdd(&g_S[n0 + tid], cS[tid]);
            atomicAdd(&g_P[n0 + tid], cP[tid]);
            atomicAdd(&g_C[n0 + tid], cC[tid]);
        }
    }
}

// 64 blocks x 128 threads; last block finalizes via ticket.
__global__ void reduce_kernel(float* __restrict__ out) {
    const int tid = threadIdx.x;
    const int r = blockIdx.x * 128 + tid;
    float loss = 0.f; int cnt = 0;
    const int c = g_C[r];
    if (c > 0) { loss = logf(g_S[r]) - g_P[r] / (float)c; cnt = 1; }
#pragma unroll
    for (int o = 16; o > 0; o >>= 1) {
        loss += __shfl_down_sync(0xFFFFFFFFu, loss, o);
        cnt  += __shfl_down_sync(0xFFFFFFFFu, cnt, o);
    }
    __shared__ float sl[4];
    __shared__ int   sc[4];
    if ((tid & 31) == 0) { sl[tid >> 5] = loss; sc[tid >> 5] = cnt; }
    __syncthreads();
    if (tid == 0) {
        float L = sl[0] + sl[1] + sl[2] + sl[3];
        int   C = sc[0] + sc[1] + sc[2] + sc[3];
        atomicAdd(&g_pl, L);
        atomicAdd(&g_pc, C);
        __threadfence();
        int prev = atomicAdd(&g_ticket, 1);
        if (prev == 63) {
            float tl = atomicAdd(&g_pl, 0.f);
            int   tc = atomicAdd(&g_pc, 0);
            out[0] = tl / (float)(tc > 0 ? tc : 1);
        }
    }
}

// ---------------- launch ----------------
extern "C" void kernel_launch(void* const* d_in, const int* in_sizes, int n_in,
                              void* d_out, int out_size) {
    const float*     E      = (const float*)d_in[0];
    const long long* labels = (const long long*)d_in[1];
    float*           out    = (float*)d_out;

    cudaFuncSetAttribute(sim_kernel, cudaFuncAttributeMaxDynamicSharedMemorySize, SMEM_TOTAL);

    convert_kernel<<<(B_SIZE * D_SIZE / 4) / 256, 256>>>(E);

    dim3 grid(B_SIZE / TN, B_SIZE / TM);
    sim_kernel<<<grid, 128, SMEM_TOTAL>>>(labels);

    reduce_kernel<<<64, 128>>>(out);
}

// round 7
// speedup vs baseline: 13.1864x; 1.0368x over previous
#include <cuda_runtime.h>
#include <cuda_bf16.h>
#include <cstdint>

#define B_SIZE 8192
#define D_SIZE 1024
#define TM 128
#define TN 128
#define KC 64                      // bf16 elems per K-chunk (128 bytes/row)
#define NCHUNK (D_SIZE / KC)       // 16
#define NSTAGE 3
#define NTILES 2080                // 64*65/2 upper-triangle 128x128 tiles
#define INV_TAU 10.0f

// ---------------- device scratch (no allocations allowed) ----------------
__device__ float g_S[B_SIZE];
__device__ float g_P[B_SIZE];
__device__ int   g_C[B_SIZE];
__device__ float g_pl;
__device__ int   g_pc;
__device__ int   g_ticket;
__device__ __align__(16) __nv_bfloat16 g_Ebf[B_SIZE * D_SIZE];

// ---------------- smem layout ----------------
#define STAGE_BYTES 32768          // A tile 16KB + B tile 16KB
#define OFF_B 16384
#define SM_MISC (NSTAGE * STAGE_BYTES)
#define SM_LA  (SM_MISC + 0)       // int[128]
#define SM_LB  (SM_MISC + 512)
#define SM_RS  (SM_MISC + 1024)    // float[128]
#define SM_RP  (SM_MISC + 1536)
#define SM_RC  (SM_MISC + 2048)
#define SM_CS  (SM_MISC + 2560)
#define SM_CP  (SM_MISC + 3072)
#define SM_CC  (SM_MISC + 3584)
#define SMEM_TOTAL (SM_MISC + 4096)

// ---------------- helpers ----------------
__device__ __forceinline__ uint32_t smem_u32(const void* p) {
    uint32_t a;
    asm("{ .reg .u64 t; cvta.to.shared.u64 t, %1; cvt.u32.u64 %0, t; }" : "=r"(a) : "l"(p));
    return a;
}
__device__ __forceinline__ void cp_async16(uint32_t dst, const void* src) {
    asm volatile("cp.async.cg.shared.global [%0], [%1], 16;" :: "r"(dst), "l"(src));
}
__device__ __forceinline__ void cp_commit() { asm volatile("cp.async.commit_group;"); }

__device__ __forceinline__ void ldsm4(uint32_t addr, uint32_t* r) {
    asm volatile("ldmatrix.sync.aligned.m8n8.x4.shared.b16 {%0,%1,%2,%3}, [%4];"
                 : "=r"(r[0]), "=r"(r[1]), "=r"(r[2]), "=r"(r[3]) : "r"(addr));
}
__device__ __forceinline__ void mma16816(float* d, const uint32_t* a,
                                         uint32_t b0, uint32_t b1) {
    asm volatile(
        "mma.sync.aligned.m16n8k16.row.col.f32.bf16.bf16.f32 "
        "{%0,%1,%2,%3}, {%4,%5,%6,%7}, {%8,%9}, {%0,%1,%2,%3};"
        : "+f"(d[0]), "+f"(d[1]), "+f"(d[2]), "+f"(d[3])
        : "r"(a[0]), "r"(a[1]), "r"(a[2]), "r"(a[3]), "r"(b0), "r"(b1));
}

// ---------------- packed f32x2 fast-exp ----------------
__device__ __forceinline__ uint64_t pack2(float x) {
    uint64_t r;
    asm("mov.b64 %0, {%1, %1};" : "=l"(r) : "f"(x));
    return r;
}
// simv = acc*INV_TAU ; e = exp(simv), for a pair of elements at once.
__device__ __forceinline__ void fexp_pair(float x0, float x1,
                                          float& s0, float& s1,
                                          float& e0, float& e1) {
    const uint64_t cInv   = pack2(10.0f);                 // 1/tau
    const uint64_t cL2e   = pack2(1.4426950408889634f);
    const uint64_t cMag   = pack2(12582912.0f);           // 1.5 * 2^23
    const uint64_t cNeg1  = pack2(-1.0f);
    const uint64_t c5 = pack2(1.3333558e-3f);
    const uint64_t c4 = pack2(9.6181291e-3f);
    const uint64_t c3 = pack2(5.5504109e-2f);
    const uint64_t c2 = pack2(2.4022650e-1f);
    const uint64_t c1 = pack2(6.9314718e-1f);
    const uint64_t cOne = pack2(1.0f);

    uint64_t x2, s2, y2, t2, u2, f2, p2;
    asm("mov.b64 %0, {%1, %2};" : "=l"(x2) : "f"(x0), "f"(x1));
    asm("mul.rn.f32x2 %0, %1, %2;" : "=l"(s2) : "l"(x2), "l"(cInv));
    asm("mul.rn.f32x2 %0, %1, %2;" : "=l"(y2) : "l"(s2), "l"(cL2e));
    asm("add.rn.f32x2 %0, %1, %2;" : "=l"(t2) : "l"(y2), "l"(cMag));
    asm("fma.rn.f32x2 %0, %1, %2, %3;" : "=l"(u2) : "l"(cMag), "l"(cNeg1), "l"(t2)); // t - MAGIC
    asm("fma.rn.f32x2 %0, %1, %2, %3;" : "=l"(f2) : "l"(u2), "l"(cNeg1), "l"(y2));   // y - (t-MAGIC)
    p2 = c5;
    asm("fma.rn.f32x2 %0, %1, %2, %3;" : "=l"(p2) : "l"(p2), "l"(f2), "l"(c4));
    asm("fma.rn.f32x2 %0, %1, %2, %3;" : "=l"(p2) : "l"(p2), "l"(f2), "l"(c3));
    asm("fma.rn.f32x2 %0, %1, %2, %3;" : "=l"(p2) : "l"(p2), "l"(f2), "l"(c2));
    asm("fma.rn.f32x2 %0, %1, %2, %3;" : "=l"(p2) : "l"(p2), "l"(f2), "l"(c1));
    asm("fma.rn.f32x2 %0, %1, %2, %3;" : "=l"(p2) : "l"(p2), "l"(f2), "l"(cOne));

    uint32_t tl, th, pl, ph;
    asm("mov.b64 {%0, %1}, %2;" : "=r"(tl), "=r"(th) : "l"(t2));
    asm("mov.b64 {%0, %1}, %2;" : "=r"(pl), "=r"(ph) : "l"(p2));
    asm("mov.b64 {%0, %1}, %2;" : "=r"(*(uint32_t*)&s0), "=r"(*(uint32_t*)&s1) : "l"(s2));
    const int i0 = (int)(tl - 0x4B400000u);
    const int i1 = (int)(th - 0x4B400000u);
    e0 = __int_as_float((int)pl + (i0 << 23));
    e1 = __int_as_float((int)ph + (i1 << 23));
}

// ---------------- kernels ----------------
__global__ void convert_kernel(const float* __restrict__ E) {
    int idx = blockIdx.x * 256 + threadIdx.x;  // one float4 per thread
    if (idx < B_SIZE) { g_S[idx] = 0.f; g_P[idx] = 0.f; g_C[idx] = 0; }
    if (idx == 0) { g_pl = 0.f; g_pc = 0; g_ticket = 0; }
    float4 v = reinterpret_cast<const float4*>(E)[idx];
    __nv_bfloat162* hp = reinterpret_cast<__nv_bfloat162*>(g_Ebf);
    hp[idx * 2 + 0] = __nv_bfloat162(__float2bfloat16(v.x), __float2bfloat16(v.y));
    hp[idx * 2 + 1] = __nv_bfloat162(__float2bfloat16(v.z), __float2bfloat16(v.w));
}

__device__ __forceinline__ void load_chunk(uint32_t sb, int stage, int m0, int n0,
                                           int chunk, int tid) {
    const char* eb = reinterpret_cast<const char*>(g_Ebf);
    uint32_t sbase = sb + stage * STAGE_BYTES;
    size_t colb = (size_t)chunk * 128;
#pragma unroll
    for (int q = 0; q < 8; q++) {
        int idx = tid + q * 128;        // 0..1023
        int row = idx >> 3;             // 0..127
        int c16 = idx & 7;
        uint32_t sw = row * 128 + ((c16 * 16) ^ ((row & 7) << 4));
        size_t gA = (size_t)(m0 + row) * 2048 + colb + c16 * 16;
        size_t gB = (size_t)(n0 + row) * 2048 + colb + c16 * 16;
        cp_async16(sbase + sw, eb + gA);
        cp_async16(sbase + OFF_B + sw, eb + gB);
    }
}

__global__ void __launch_bounds__(128, 2)
sim_kernel(const long long* __restrict__ labels) {
    // linear tile index -> (bi, bj), bi <= bj, 64x64 block triangle
    const int l = blockIdx.x;
    int bi = (int)((129.0f - sqrtf(fmaxf(129.0f * 129.0f - 8.0f * (float)l, 0.f))) * 0.5f);
    if (bi > 63) bi = 63;
    while (bi > 0 && 64 * bi - (bi * (bi - 1)) / 2 > l) bi--;
    while (64 * (bi + 1) - ((bi + 1) * bi) / 2 <= l) bi++;
    const int bj = bi + (l - (64 * bi - (bi * (bi - 1)) / 2));

    extern __shared__ char smem[];
    const uint32_t sb = smem_u32(smem);
    const int tid = threadIdx.x;
    const int wid = tid >> 5, lane = tid & 31;
    const int m0 = bi * TM, n0 = bj * TN;
    const bool diagTile = (bi == bj);

    int*   lAs = reinterpret_cast<int*>(smem + SM_LA);
    int*   lBs = reinterpret_cast<int*>(smem + SM_LB);
    float* rS = reinterpret_cast<float*>(smem + SM_RS);
    float* rP = reinterpret_cast<float*>(smem + SM_RP);
    int*   rC = reinterpret_cast<int*>(smem + SM_RC);
    float* cS = reinterpret_cast<float*>(smem + SM_CS);
    float* cP = reinterpret_cast<float*>(smem + SM_CP);
    int*   cC = reinterpret_cast<int*>(smem + SM_CC);

    if (tid < 128) {
        lAs[tid] = (int)labels[m0 + tid];
        lBs[tid] = (int)labels[n0 + tid];
        rS[tid] = 0.f; rP[tid] = 0.f; rC[tid] = 0;
        cS[tid] = 0.f; cP[tid] = 0.f; cC[tid] = 0;
    }

    // 4 warps, 2x2; warp tile = 64 rows x 64 cols
    const int wr = wid >> 1, wc = wid & 1;
    const int qr = lane >> 2, qc = lane & 3;
    const uint32_t xmask = (lane & 7) << 4;
    const uint32_t rsel = lane & 15;
    const uint32_t csel = (lane >> 4) << 4;
    uint32_t a_row[4], b_row[4];
#pragma unroll
    for (int g = 0; g < 4; g++) {
        a_row[g] = (wr * 64 + g * 16 + rsel) * 128;
        b_row[g] = (wc * 64 + g * 16 + rsel) * 128 + OFF_B;
    }

    float acc[4][8][4];
#pragma unroll
    for (int i = 0; i < 4; i++)
#pragma unroll
        for (int j = 0; j < 8; j++)
#pragma unroll
            for (int k = 0; k < 4; k++) acc[i][j][k] = 0.f;

    load_chunk(sb, 0, m0, n0, 0, tid); cp_commit();
    load_chunk(sb, 1, m0, n0, 1, tid); cp_commit();

    uint32_t a[2][4][4], b[2][4][4];   // register double buffer

    for (int t = 0; t < NCHUNK; t++) {
        if (t < NCHUNK - 1) asm volatile("cp.async.wait_group 1;" ::: "memory");
        else                asm volatile("cp.async.wait_group 0;" ::: "memory");
        __syncthreads();

        const uint32_t stg = sb + (t - NSTAGE * (t / NSTAGE)) * STAGE_BYTES;

        // preload ks=0 fragments
        {
            const uint32_t co = csel ^ xmask;
#pragma unroll
            for (int g = 0; g < 4; g++) ldsm4(stg + a_row[g] + co, a[0][g]);
#pragma unroll
            for (int g = 0; g < 4; g++) ldsm4(stg + b_row[g] + co, b[0][g]);
        }

        // prefetch chunk t+2 (overlaps with the HMMA work below)
        if (t + 2 < NCHUNK) {
            int ps = t + 2 - NSTAGE * ((t + 2) / NSTAGE);
            load_chunk(sb, ps, m0, n0, t + 2, tid);
            cp_commit();
        }

#pragma unroll
        for (int ks = 0; ks < 4; ks++) {
            const int cur = ks & 1, nxt = cur ^ 1;
            if (ks < 3) {
                const uint32_t co = ((ks + 1) * 32 + csel) ^ xmask;
#pragma unroll
                for (int g = 0; g < 4; g++) ldsm4(stg + a_row[g] + co, a[nxt][g]);
#pragma unroll
                for (int g = 0; g < 4; g++) ldsm4(stg + b_row[g] + co, b[nxt][g]);
            }
#pragma unroll
            for (int i = 0; i < 4; i++)
#pragma unroll
                for (int j = 0; j < 8; j++)
                    mma16816(acc[i][j], a[cur][i],
                             b[cur][j >> 1][j & 1], b[cur][j >> 1][(j & 1) + 2]);
        }
    }

    // ---- fused epilogue (f32x2 exp on element pairs) ----
    int rowl[8], la[8];
#pragma unroll
    for (int i = 0; i < 4; i++)
#pragma unroll
        for (int h = 0; h < 2; h++) {
            int ri = i * 2 + h;
            rowl[ri] = wr * 64 + i * 16 + h * 8 + qr;
            la[ri] = lAs[rowl[ri]];
        }
    float rs[8], rp[8]; int rc[8];
#pragma unroll
    for (int ri = 0; ri < 8; ri++) { rs[ri] = 0.f; rp[ri] = 0.f; rc[ri] = 0; }

#pragma unroll
    for (int j = 0; j < 8; j++) {
        const int lc0 = wc * 64 + j * 8 + qc * 2;
        const int lc1 = lc0 + 1;
        const int lb0 = lBs[lc0], lb1 = lBs[lc1];
        float cs0 = 0.f, cp0 = 0.f, cs1 = 0.f, cp1 = 0.f;
        int cct0 = 0, cct1 = 0;
#pragma unroll
        for (int i = 0; i < 4; i++)
#pragma unroll
            for (int h = 0; h < 2; h++) {
                const int ri = i * 2 + h;
                float s0, s1, e0, e1;
                fexp_pair(acc[i][j][h * 2], acc[i][j][h * 2 + 1], s0, s1, e0, e1);
                if (!(diagTile && (rowl[ri] == lc0))) {
                    rs[ri] += e0;
                    const bool pos = (lb0 == la[ri]);
                    if (pos) { rp[ri] += s0; rc[ri]++; cp0 += s0; cct0++; }
                    cs0 += e0;
                }
                if (!(diagTile && (rowl[ri] == lc1))) {
                    rs[ri] += e1;
                    const bool pos = (lb1 == la[ri]);
                    if (pos) { rp[ri] += s1; rc[ri]++; cp1 += s1; cct1++; }
                    cs1 += e1;
                }
            }
        if (!diagTile) {
            // reduce across qr lanes (stride 4): 8 partials -> 1
#pragma unroll
            for (int o = 4; o <= 16; o <<= 1) {
                cs0  += __shfl_xor_sync(0xFFFFFFFFu, cs0, o);
                cp0  += __shfl_xor_sync(0xFFFFFFFFu, cp0, o);
                cct0 += __shfl_xor_sync(0xFFFFFFFFu, cct0, o);
                cs1  += __shfl_xor_sync(0xFFFFFFFFu, cs1, o);
                cp1  += __shfl_xor_sync(0xFFFFFFFFu, cp1, o);
                cct1 += __shfl_xor_sync(0xFFFFFFFFu, cct1, o);
            }
            if (qr == 0) {
                atomicAdd(&cS[lc0], cs0);
                atomicAdd(&cP[lc0], cp0);
                atomicAdd(&cC[lc0], cct0);
                atomicAdd(&cS[lc1], cs1);
                atomicAdd(&cP[lc1], cp1);
                atomicAdd(&cC[lc1], cct1);
            }
        }
    }
    // reduce row stats across qc lanes (stride 1): 4 partials -> 1
#pragma unroll
    for (int ri = 0; ri < 8; ri++) {
#pragma unroll
        for (int o = 1; o <= 2; o <<= 1) {
            rs[ri] += __shfl_xor_sync(0xFFFFFFFFu, rs[ri], o);
            rp[ri] += __shfl_xor_sync(0xFFFFFFFFu, rp[ri], o);
            rc[ri] += __shfl_xor_sync(0xFFFFFFFFu, rc[ri], o);
        }
        if (qc == 0) {
            atomicAdd(&rS[rowl[ri]], rs[ri]);
            atomicAdd(&rP[rowl[ri]], rp[ri]);
            atomicAdd(&rC[rowl[ri]], rc[ri]);
        }
    }
    __syncthreads();

    if (tid < 128) {
        atomicAdd(&g_S[m0 + tid], rS[tid]);
        atomicAdd(&g_P[m0 + tid], rP[tid]);
        atomicAdd(&g_C[m0 + tid], rC[tid]);
        if (!diagTile) {
            atomicAdd(&g_S[n0 + tid], cS[tid]);
            atomicAdd(&g_P[n0 + tid], cP[tid]);
            atomicAdd(&g_C[n0 + tid], cC[tid]);
        }
    }
}

// 64 blocks x 128 threads; last block finalizes via ticket.
__global__ void reduce_kernel(float* __restrict__ out) {
    const int tid = threadIdx.x;
    const int r = blockIdx.x * 128 + tid;
    float loss = 0.f; int cnt = 0;
    const int c = g_C[r];
    if (c > 0) { loss = logf(g_S[r]) - g_P[r] / (float)c; cnt = 1; }
#pragma unroll
    for (int o = 16; o > 0; o >>= 1) {
        loss += __shfl_down_sync(0xFFFFFFFFu, loss, o);
        cnt  += __shfl_down_sync(0xFFFFFFFFu, cnt, o);
    }
    __shared__ float sl[4];
    __shared__ int   sc[4];
    if ((tid & 31) == 0) { sl[tid >> 5] = loss; sc[tid >> 5] = cnt; }
    __syncthreads();
    if (tid == 0) {
        float L = sl[0] + sl[1] + sl[2] + sl[3];
        int   C = sc[0] + sc[1] + sc[2] + sc[3];
        atomicAdd(&g_pl, L);
        atomicAdd(&g_pc, C);
        __threadfence();
        int prev = atomicAdd(&g_ticket, 1);
        if (prev == 63) {
            float tl = atomicAdd(&g_pl, 0.f);
            int   tc = atomicAdd(&g_pc, 0);
            out[0] = tl / (float)(tc > 0 ? tc : 1);
        }
    }
}

// ---------------- launch ----------------
extern "C" void kernel_launch(void* const* d_in, const int* in_sizes, int n_in,
                              void* d_out, int out_size) {
    const float*     E      = (const float*)d_in[0];
    const long long* labels = (const long long*)d_in[1];
    float*           out    = (float*)d_out;

    cudaFuncSetAttribute(sim_kernel, cudaFuncAttributeMaxDynamicSharedMemorySize, SMEM_TOTAL);

    convert_kernel<<<(B_SIZE * D_SIZE / 4) / 256, 256>>>(E);

    sim_kernel<<<NTILES, 128, SMEM_TOTAL>>>(labels);

    reduce_kernel<<<64, 128>>>(out);
}